// round 9
// baseline (speedup 1.0000x reference)
#include <cuda_runtime.h>
#include <cuda_bf16.h>
#include <cstdint>
#include <cstddef>

#define NNODES 100000
#define NLAST  (NNODES - 1)
#define NWORDS 3125            // ceil(100000/32)
#define CAP1   4096
#define CAP2   32768
#define GRID   148
#define TPB    512

// ---- scratch (device globals; zero at load; cleaned at kernel end) --------
__device__ int           g_deg[NNODES];
__device__ float         g_s[NNODES];
__device__ int           g_s1[CAP1];
__device__ int           g_pair_src[CAP2];
__device__ int           g_pair_dst[CAP2];
__device__ int           g_count1;
__device__ int           g_count2;
__device__ unsigned int           g_bar_count;
__device__ volatile unsigned int  g_bar_gen;
__device__ volatile unsigned int  g_done;

// ---- software grid barrier ------------------------------------------------
__device__ __forceinline__ void grid_barrier() {
    __syncthreads();
    if (threadIdx.x == 0) {
        __threadfence();
        unsigned gen = g_bar_gen;
        unsigned arrived = atomicAdd(&g_bar_count, 1u);
        if (arrived == GRID - 1) {
            g_bar_count = 0u;
            __threadfence();
            g_bar_gen = gen + 1u;
        } else {
            while (g_bar_gen == gen) { }
        }
        __threadfence();
    }
    __syncthreads();
}

#define BM_TEST(bm, v)  (((bm)[(v) >> 5] >> ((v) & 31)) & 1u)

// batch-of-8 strided scan over int4 dst vector; body sees (d4, idx4)
#define SCAN8_I32(...)                                                          \
    {                                                                           \
        const int step = nthreads;                                              \
        int base = tid;                                                         \
        int rem = (tid < nv) ? ((nv - tid + step - 1) / step) : 0;              \
        while (rem > 0) {                                                       \
            int m = rem < 8 ? rem : 8;                                          \
            int4 v[8];                                                          \
            _Pragma("unroll")                                                   \
            for (int k = 0; k < 8; k++) if (k < m) v[k] = dv[base + k * step];  \
            _Pragma("unroll")                                                   \
            for (int k = 0; k < 8; k++) if (k < m) {                            \
                int idx4 = base + k * step; int4 d4 = v[k]; __VA_ARGS__;        \
            }                                                                   \
            base += 8 * step; rem -= m;                                         \
        }                                                                       \
    }

// batch-of-8 strided scan over ulonglong2 dst vector; body sees (d2, idx2)
#define SCAN8_I64(...)                                                          \
    {                                                                           \
        const int step = nthreads;                                              \
        int base = tid;                                                         \
        int rem = (tid < nv) ? ((nv - tid + step - 1) / step) : 0;              \
        while (rem > 0) {                                                       \
            int m = rem < 8 ? rem : 8;                                          \
            ulonglong2 v[8];                                                    \
            _Pragma("unroll")                                                   \
            for (int k = 0; k < 8; k++) if (k < m) v[k] = dv[base + k * step];  \
            _Pragma("unroll")                                                   \
            for (int k = 0; k < 8; k++) if (k < m) {                            \
                int idx2 = base + k * step; ulonglong2 d2 = v[k]; __VA_ARGS__;  \
            }                                                                   \
            base += 8 * step; rem -= m;                                         \
        }                                                                       \
    }

// ---------------------------------------------------------------------------
__global__ void __launch_bounds__(TPB, 1)
gcn_fused_kernel(const void* __restrict__ eidx,
                 const float* __restrict__ x,
                 const float* __restrict__ W1, const float* __restrict__ b1,
                 const float* __restrict__ W2, const float* __restrict__ b2,
                 const float* __restrict__ Wfc, const float* __restrict__ bfc,
                 float* __restrict__ out, int E) {
    const int tid      = blockIdx.x * TPB + threadIdx.x;
    const int nthreads = GRID * TPB;

    __shared__ unsigned int s_bm[NWORDS];
    __shared__ int sh_mode;

    // per-block dtype detect (same 256B in every block; L2 broadcast)
    if (threadIdx.x == 0) {
        const unsigned int* w = (const unsigned int*)eidx;
        int all0 = 1;
        #pragma unroll
        for (int i = 0; i < 32; i++)
            if (w[2 * i + 1] != 0u) all0 = 0;
        sh_mode = all0;
    }
    for (int wdx = threadIdx.x; wdx < NWORDS; wdx += TPB) s_bm[wdx] = 0u;
    __syncthreads();
    const int mode = sh_mode;

    // ================= P1: scan — edges with dst == N-1 ====================
    if (mode) {
        const long long* __restrict__ srcp = (const long long*)eidx;
        const long long* __restrict__ dstp = srcp + E;
        const int nv = E >> 1;
        const ulonglong2* __restrict__ dv = (const ulonglong2*)dstp;
        SCAN8_I64(
            if ((int)d2.x == NLAST) { int p = atomicAdd(&g_count1, 1); if (p < CAP1) g_s1[p] = (int)srcp[2*idx2];   }
            if ((int)d2.y == NLAST) { int p = atomicAdd(&g_count1, 1); if (p < CAP1) g_s1[p] = (int)srcp[2*idx2+1]; }
        )
        for (int e = (nv << 1) + tid; e < E; e += nthreads) {
            if ((int)dstp[e] == NLAST) { int p = atomicAdd(&g_count1, 1); if (p < CAP1) g_s1[p] = (int)srcp[e]; }
        }
    } else {
        const int* __restrict__ srcp = (const int*)eidx;
        const int* __restrict__ dstp = srcp + E;
        const int nv = (((unsigned long long)(size_t)dstp & 15ull) == 0ull) ? (E >> 2) : 0;
        const int4* __restrict__ dv = (const int4*)dstp;
        SCAN8_I32(
            if (d4.x == NLAST) { int p = atomicAdd(&g_count1, 1); if (p < CAP1) g_s1[p] = srcp[4*idx4+0]; }
            if (d4.y == NLAST) { int p = atomicAdd(&g_count1, 1); if (p < CAP1) g_s1[p] = srcp[4*idx4+1]; }
            if (d4.z == NLAST) { int p = atomicAdd(&g_count1, 1); if (p < CAP1) g_s1[p] = srcp[4*idx4+2]; }
            if (d4.w == NLAST) { int p = atomicAdd(&g_count1, 1); if (p < CAP1) g_s1[p] = srcp[4*idx4+3]; }
        )
        for (int e = (nv << 2) + tid; e < E; e += nthreads) {
            if (dstp[e] == NLAST) { int p = atomicAdd(&g_count1, 1); if (p < CAP1) g_s1[p] = srcp[e]; }
        }
    }
    grid_barrier();   // barrier #1

    // build needed bitmask per-block in smem from g_s1
    {
        int c1 = g_count1; if (c1 > CAP1) c1 = CAP1;
        for (int k = threadIdx.x; k < c1; k += TPB) {
            int u = g_s1[k];
            atomicOr(&s_bm[u >> 5], 1u << (u & 31));
        }
        if (threadIdx.x == 0) atomicOr(&s_bm[NLAST >> 5], 1u << (NLAST & 31));
    }
    __syncthreads();

    // ================= P3: scan — edges into needed set ====================
    if (mode) {
        const long long* __restrict__ srcp = (const long long*)eidx;
        const long long* __restrict__ dstp = srcp + E;
        const int nv = E >> 1;
        const ulonglong2* __restrict__ dv = (const ulonglong2*)dstp;
        SCAN8_I64(
            int d0 = (int)d2.x;
            int d1 = (int)d2.y;
            if (BM_TEST(s_bm, d0)) { int s = (int)srcp[2*idx2];   int p = atomicAdd(&g_count2, 1); if (p < CAP2) { g_pair_src[p] = s; g_pair_dst[p] = d0; } }
            if (BM_TEST(s_bm, d1)) { int s = (int)srcp[2*idx2+1]; int p = atomicAdd(&g_count2, 1); if (p < CAP2) { g_pair_src[p] = s; g_pair_dst[p] = d1; } }
        )
        for (int e = (nv << 1) + tid; e < E; e += nthreads) {
            int d = (int)dstp[e];
            if (BM_TEST(s_bm, d)) { int s = (int)srcp[e]; int p = atomicAdd(&g_count2, 1); if (p < CAP2) { g_pair_src[p] = s; g_pair_dst[p] = d; } }
        }
    } else {
        const int* __restrict__ srcp = (const int*)eidx;
        const int* __restrict__ dstp = srcp + E;
        const int nv = (((unsigned long long)(size_t)dstp & 15ull) == 0ull) ? (E >> 2) : 0;
        const int4* __restrict__ dv = (const int4*)dstp;
        SCAN8_I32(
            if (BM_TEST(s_bm, d4.x)) { int s = srcp[4*idx4+0]; int p = atomicAdd(&g_count2, 1); if (p < CAP2) { g_pair_src[p] = s; g_pair_dst[p] = d4.x; } }
            if (BM_TEST(s_bm, d4.y)) { int s = srcp[4*idx4+1]; int p = atomicAdd(&g_count2, 1); if (p < CAP2) { g_pair_src[p] = s; g_pair_dst[p] = d4.y; } }
            if (BM_TEST(s_bm, d4.z)) { int s = srcp[4*idx4+2]; int p = atomicAdd(&g_count2, 1); if (p < CAP2) { g_pair_src[p] = s; g_pair_dst[p] = d4.z; } }
            if (BM_TEST(s_bm, d4.w)) { int s = srcp[4*idx4+3]; int p = atomicAdd(&g_count2, 1); if (p < CAP2) { g_pair_src[p] = s; g_pair_dst[p] = d4.w; } }
        )
        for (int e = (nv << 2) + tid; e < E; e += nthreads) {
            int d = dstp[e];
            if (BM_TEST(s_bm, d)) { int s = srcp[e]; int p = atomicAdd(&g_count2, 1); if (p < CAP2) { g_pair_src[p] = s; g_pair_dst[p] = d; } }
        }
    }
    grid_barrier();   // barrier #2

    // extend bitmask with pair srcs -> need_deg set
    {
        int c2 = g_count2; if (c2 > CAP2) c2 = CAP2;
        for (int k = threadIdx.x; k < c2; k += TPB) {
            int u = g_pair_src[k];
            atomicOr(&s_bm[u >> 5], 1u << (u & 31));
        }
    }
    __syncthreads();

    // ================= P4: filtered degree scan ============================
    if (mode) {
        const long long* __restrict__ dstp = (const long long*)eidx + E;
        const int nv = E >> 1;
        const ulonglong2* __restrict__ dv = (const ulonglong2*)dstp;
        SCAN8_I64(
            (void)idx2;
            int d0 = (int)d2.x;
            int d1 = (int)d2.y;
            if (BM_TEST(s_bm, d0)) atomicAdd(&g_deg[d0], 1);
            if (BM_TEST(s_bm, d1)) atomicAdd(&g_deg[d1], 1);
        )
        for (int e = (nv << 1) + tid; e < E; e += nthreads) {
            int d = (int)dstp[e];
            if (BM_TEST(s_bm, d)) atomicAdd(&g_deg[d], 1);
        }
    } else {
        const int* __restrict__ dstp = (const int*)eidx + E;
        const int nv = (((unsigned long long)(size_t)dstp & 15ull) == 0ull) ? (E >> 2) : 0;
        const int4* __restrict__ dv = (const int4*)dstp;
        SCAN8_I32(
            (void)idx4;
            if (BM_TEST(s_bm, d4.x)) atomicAdd(&g_deg[d4.x], 1);
            if (BM_TEST(s_bm, d4.y)) atomicAdd(&g_deg[d4.y], 1);
            if (BM_TEST(s_bm, d4.z)) atomicAdd(&g_deg[d4.z], 1);
            if (BM_TEST(s_bm, d4.w)) atomicAdd(&g_deg[d4.w], 1);
        )
        for (int e = (nv << 2) + tid; e < E; e += nthreads) {
            int d = dstp[e];
            if (BM_TEST(s_bm, d)) atomicAdd(&g_deg[d], 1);
        }
    }

    // ---- final sync: done-counter; non-zero blocks arrive and EXIT --------
    __syncthreads();
    if (blockIdx.x != 0) {
        if (threadIdx.x == 0) {
            __threadfence();
            atomicAdd((unsigned int*)&g_done, 1u);
        }
        return;
    }
    if (threadIdx.x == 0) {
        __threadfence();
        while (g_done < GRID - 1) { }
        __threadfence();
    }
    __syncthreads();

    // ================= P5+P6+cleanup: block 0 only =========================
    {
        int c1 = g_count1; if (c1 > CAP1) c1 = CAP1;
        int c2 = g_count2; if (c2 > CAP2) c2 = CAP2;

        // P5: layer-1 aggregation over pairs
        for (int k = threadIdx.x; k < c2; k += TPB) {
            int s = g_pair_src[k];
            int d = g_pair_dst[k];
            float dis = rsqrtf((float)(__ldcg(&g_deg[s]) + 1));
            float did = rsqrtf((float)(__ldcg(&g_deg[d]) + 1));
            atomicAdd(&g_s[d], x[s] * dis * did);
        }
        __syncthreads();
        __threadfence();

        // P6: layer-2 @ node N-1 + fc head (warp 0)
        if (threadIdx.x < 32) {
            int lane = threadIdx.x;
            __shared__ float sW1[16], sb1[16], sW2[128], sb2[8], sWfc[8];
            if (lane < 16) { sW1[lane] = W1[lane]; sb1[lane] = b1[lane]; }
            if (lane < 8)  { sb2[lane] = b2[lane]; sWfc[lane] = Wfc[lane]; }
            for (int k = lane; k < 128; k += 32) sW2[k] = W2[k];
            __syncwarp();

            const float dinvL = rsqrtf((float)(__ldcg(&g_deg[NLAST]) + 1));

            float agg[8];
            #pragma unroll
            for (int j = 0; j < 8; j++) agg[j] = 0.0f;

            // k in [0, c1): real edges into N-1; k == c1: appended self-loop.
            for (int k = lane; k <= c1; k += 32) {
                int u = (k == c1) ? NLAST : g_s1[k];
                float du = rsqrtf((float)(__ldcg(&g_deg[u]) + 1));
                float norm = du * dinvL;
                float su = __ldcg(&g_s[u]) + x[u] * du * du;
                float h1[16];
                #pragma unroll
                for (int j = 0; j < 16; j++)
                    h1[j] = fmaxf(fmaf(su, sW1[j], sb1[j]), 0.0f);
                #pragma unroll
                for (int j = 0; j < 8; j++) {
                    float v = 0.0f;
                    #pragma unroll
                    for (int t = 0; t < 16; t++) v = fmaf(h1[t], sW2[t * 8 + j], v);
                    agg[j] = fmaf(v, norm, agg[j]);
                }
            }
            #pragma unroll
            for (int off = 16; off > 0; off >>= 1) {
                #pragma unroll
                for (int j = 0; j < 8; j++)
                    agg[j] += __shfl_down_sync(0xffffffff, agg[j], off);
            }
            if (lane == 0) {
                float o = bfc[0];
                #pragma unroll
                for (int j = 0; j < 8; j++) {
                    float h2 = fmaxf(agg[j] + sb2[j], 0.0f);
                    o = fmaf(h2, sWfc[j], o);
                }
                out[0] = o;
            }
        }
        __syncthreads();

        // cleanup: zero all touched scratch for the next replay
        for (int k = threadIdx.x; k < c1; k += TPB) {
            int u = g_s1[k];
            g_deg[u] = 0; g_s[u] = 0.0f;
        }
        for (int k = threadIdx.x; k < c2; k += TPB) {
            int s = g_pair_src[k], d = g_pair_dst[k];
            g_deg[s] = 0; g_s[s] = 0.0f;
            g_deg[d] = 0; g_s[d] = 0.0f;
        }
        if (threadIdx.x == 0) {
            g_deg[NLAST] = 0; g_s[NLAST] = 0.0f;
            g_count1 = 0; g_count2 = 0;
            g_done = 0u;
        }
    }
}

// ---------------------------------------------------------------------------
extern "C" void kernel_launch(void* const* d_in, const int* in_sizes, int n_in,
                              void* d_out, int out_size) {
    const float* x    = (const float*)d_in[0];
    const void*  eidx = d_in[1];
    const float* W1   = (const float*)d_in[2];
    const float* b1   = (const float*)d_in[3];
    const float* W2   = (const float*)d_in[4];
    const float* b2   = (const float*)d_in[5];
    const float* Wfc  = (const float*)d_in[6];
    const float* bfc  = (const float*)d_in[7];
    float* out = (float*)d_out;

    int E = in_sizes[1] / 2;

    gcn_fused_kernel<<<GRID, TPB>>>(eidx, x, W1, b1, W2, b2, Wfc, bfc, out, E);
}

// round 10
// speedup vs baseline: 1.0656x; 1.0656x over previous
#include <cuda_runtime.h>
#include <cuda_bf16.h>
#include <cstdint>
#include <cstddef>

#define NNODES 100000
#define NLAST  (NNODES - 1)
#define NWORDS 3125            // ceil(100000/32)
#define CAP1   4096
#define CAP2   32768
#define GRID   148
#define TPB    1024
#define NTHREADS (GRID * TPB)

// ---- scratch (device globals; zero at load; cleaned at kernel end) --------
__device__ int           g_deg[NNODES];
__device__ float         g_s[NNODES];
__device__ int           g_s1[CAP1];
__device__ int2          g_pair[CAP2];
__device__ int           g_count1;
__device__ int           g_count2;
__device__ unsigned int           g_bar_count;
__device__ volatile unsigned int  g_bar_gen;
__device__ volatile unsigned int  g_done;

// ---- software grid barrier ------------------------------------------------
__device__ __forceinline__ void grid_barrier() {
    __syncthreads();
    if (threadIdx.x == 0) {
        __threadfence();
        unsigned gen = g_bar_gen;
        unsigned arrived = atomicAdd(&g_bar_count, 1u);
        if (arrived == GRID - 1) {
            g_bar_count = 0u;
            __threadfence();
            g_bar_gen = gen + 1u;
        } else {
            while (g_bar_gen == gen) { }
        }
        __threadfence();
    }
    __syncthreads();
}

#define BM_TEST(bm, v)  (((bm)[(v) >> 5] >> ((v) & 31)) & 1u)

// One-shot predicated scan (int32 mode): each thread issues up to 6
// independent int4 loads covering the whole dst vector, then runs the tests.
// BODY sees (d4, idx4) and is only executed for valid slots.
#define SCAN6_I32(...)                                                          \
    {                                                                           \
        int4 v[6];                                                              \
        int  ii[6];                                                             \
        _Pragma("unroll")                                                       \
        for (int k = 0; k < 6; k++) {                                           \
            ii[k] = tid + k * NTHREADS;                                         \
            if (ii[k] < nv) v[k] = dv[ii[k]];                                   \
        }                                                                       \
        _Pragma("unroll")                                                       \
        for (int k = 0; k < 6; k++) {                                           \
            if (ii[k] < nv) { int idx4 = ii[k]; int4 d4 = v[k]; __VA_ARGS__; }  \
        }                                                                       \
    }

// ---------------------------------------------------------------------------
__global__ void __launch_bounds__(TPB, 1)
gcn_fused_kernel(const void* __restrict__ eidx,
                 const float* __restrict__ x,
                 const float* __restrict__ W1, const float* __restrict__ b1,
                 const float* __restrict__ W2, const float* __restrict__ b2,
                 const float* __restrict__ Wfc, const float* __restrict__ bfc,
                 float* __restrict__ out, int E) {
    const int tid = blockIdx.x * TPB + threadIdx.x;

    __shared__ unsigned int s_bm[NWORDS];
    __shared__ int sh_mode;

    // per-block dtype detect (same 256B everywhere; L2 broadcast)
    if (threadIdx.x == 0) {
        const unsigned int* w = (const unsigned int*)eidx;
        int all0 = 1;
        #pragma unroll
        for (int i = 0; i < 32; i++)
            if (w[2 * i + 1] != 0u) all0 = 0;
        sh_mode = all0;
    }
    for (int wdx = threadIdx.x; wdx < NWORDS; wdx += TPB) s_bm[wdx] = 0u;
    __syncthreads();
    const int mode = sh_mode;

    // int32 fast path uses one-shot scans only when the full dst vector is
    // int4-aligned and 6 loads/thread cover it.
    const int* __restrict__ srcp32 = (const int*)eidx;
    const int* __restrict__ dstp32 = srcp32 + E;
    const int nv32 = (!mode && ((unsigned long long)(size_t)dstp32 & 15ull) == 0ull &&
                      (E & 3) == 0 && (E >> 2) <= 6 * NTHREADS) ? (E >> 2) : 0;

    // ================= P1: scan — edges with dst == N-1 ====================
    if (!mode && nv32) {
        const int nv = nv32;
        const int4* __restrict__ dv = (const int4*)dstp32;
        SCAN6_I32(
            if (d4.x == NLAST) { int p = atomicAdd(&g_count1, 1); if (p < CAP1) g_s1[p] = srcp32[4*idx4+0]; }
            if (d4.y == NLAST) { int p = atomicAdd(&g_count1, 1); if (p < CAP1) g_s1[p] = srcp32[4*idx4+1]; }
            if (d4.z == NLAST) { int p = atomicAdd(&g_count1, 1); if (p < CAP1) g_s1[p] = srcp32[4*idx4+2]; }
            if (d4.w == NLAST) { int p = atomicAdd(&g_count1, 1); if (p < CAP1) g_s1[p] = srcp32[4*idx4+3]; }
        )
    } else if (mode) {
        const long long* __restrict__ srcp = (const long long*)eidx;
        const long long* __restrict__ dstp = srcp + E;
        const int nv = E >> 1;
        const ulonglong2* __restrict__ dv = (const ulonglong2*)dstp;
        for (int i = tid; i < nv; i += NTHREADS) {
            ulonglong2 d2 = dv[i];
            if ((int)d2.x == NLAST) { int p = atomicAdd(&g_count1, 1); if (p < CAP1) g_s1[p] = (int)srcp[2*i];   }
            if ((int)d2.y == NLAST) { int p = atomicAdd(&g_count1, 1); if (p < CAP1) g_s1[p] = (int)srcp[2*i+1]; }
        }
        for (int e = (nv << 1) + tid; e < E; e += NTHREADS) {
            if ((int)dstp[e] == NLAST) { int p = atomicAdd(&g_count1, 1); if (p < CAP1) g_s1[p] = (int)srcp[e]; }
        }
    } else {
        for (int e = tid; e < E; e += NTHREADS) {
            if (dstp32[e] == NLAST) { int p = atomicAdd(&g_count1, 1); if (p < CAP1) g_s1[p] = srcp32[e]; }
        }
    }
    grid_barrier();   // barrier #1

    // build needed bitmask per-block in smem from g_s1
    {
        int c1 = g_count1; if (c1 > CAP1) c1 = CAP1;
        for (int k = threadIdx.x; k < c1; k += TPB) {
            int u = g_s1[k];
            atomicOr(&s_bm[u >> 5], 1u << (u & 31));
        }
        if (threadIdx.x == 0) atomicOr(&s_bm[NLAST >> 5], 1u << (NLAST & 31));
    }
    __syncthreads();

    // ================= P3: scan — edges into needed set ====================
    if (!mode && nv32) {
        const int nv = nv32;
        const int4* __restrict__ dv = (const int4*)dstp32;
        SCAN6_I32(
            if (BM_TEST(s_bm, d4.x)) { int p = atomicAdd(&g_count2, 1); if (p < CAP2) g_pair[p] = make_int2(srcp32[4*idx4+0], d4.x); }
            if (BM_TEST(s_bm, d4.y)) { int p = atomicAdd(&g_count2, 1); if (p < CAP2) g_pair[p] = make_int2(srcp32[4*idx4+1], d4.y); }
            if (BM_TEST(s_bm, d4.z)) { int p = atomicAdd(&g_count2, 1); if (p < CAP2) g_pair[p] = make_int2(srcp32[4*idx4+2], d4.z); }
            if (BM_TEST(s_bm, d4.w)) { int p = atomicAdd(&g_count2, 1); if (p < CAP2) g_pair[p] = make_int2(srcp32[4*idx4+3], d4.w); }
        )
    } else if (mode) {
        const long long* __restrict__ srcp = (const long long*)eidx;
        const long long* __restrict__ dstp = srcp + E;
        const int nv = E >> 1;
        const ulonglong2* __restrict__ dv = (const ulonglong2*)dstp;
        for (int i = tid; i < nv; i += NTHREADS) {
            ulonglong2 d2 = dv[i];
            int d0 = (int)d2.x;
            int d1 = (int)d2.y;
            if (BM_TEST(s_bm, d0)) { int p = atomicAdd(&g_count2, 1); if (p < CAP2) g_pair[p] = make_int2((int)srcp[2*i],   d0); }
            if (BM_TEST(s_bm, d1)) { int p = atomicAdd(&g_count2, 1); if (p < CAP2) g_pair[p] = make_int2((int)srcp[2*i+1], d1); }
        }
        for (int e = (nv << 1) + tid; e < E; e += NTHREADS) {
            int d = (int)dstp[e];
            if (BM_TEST(s_bm, d)) { int p = atomicAdd(&g_count2, 1); if (p < CAP2) g_pair[p] = make_int2((int)srcp[e], d); }
        }
    } else {
        for (int e = tid; e < E; e += NTHREADS) {
            int d = dstp32[e];
            if (BM_TEST(s_bm, d)) { int p = atomicAdd(&g_count2, 1); if (p < CAP2) g_pair[p] = make_int2(srcp32[e], d); }
        }
    }
    grid_barrier();   // barrier #2

    // extend bitmask with pair srcs -> need_deg set
    {
        int c2 = g_count2; if (c2 > CAP2) c2 = CAP2;
        for (int k = threadIdx.x; k < c2; k += TPB) {
            int u = g_pair[k].x;
            atomicOr(&s_bm[u >> 5], 1u << (u & 31));
        }
    }
    __syncthreads();

    // ================= P4: filtered degree scan ============================
    if (!mode && nv32) {
        const int nv = nv32;
        const int4* __restrict__ dv = (const int4*)dstp32;
        SCAN6_I32(
            (void)idx4;
            if (BM_TEST(s_bm, d4.x)) atomicAdd(&g_deg[d4.x], 1);
            if (BM_TEST(s_bm, d4.y)) atomicAdd(&g_deg[d4.y], 1);
            if (BM_TEST(s_bm, d4.z)) atomicAdd(&g_deg[d4.z], 1);
            if (BM_TEST(s_bm, d4.w)) atomicAdd(&g_deg[d4.w], 1);
        )
    } else if (mode) {
        const long long* __restrict__ dstp = (const long long*)eidx + E;
        const int nv = E >> 1;
        const ulonglong2* __restrict__ dv = (const ulonglong2*)dstp;
        for (int i = tid; i < nv; i += NTHREADS) {
            ulonglong2 d2 = dv[i];
            int d0 = (int)d2.x;
            int d1 = (int)d2.y;
            if (BM_TEST(s_bm, d0)) atomicAdd(&g_deg[d0], 1);
            if (BM_TEST(s_bm, d1)) atomicAdd(&g_deg[d1], 1);
        }
        for (int e = (nv << 1) + tid; e < E; e += NTHREADS) {
            int d = (int)dstp[e];
            if (BM_TEST(s_bm, d)) atomicAdd(&g_deg[d], 1);
        }
    } else {
        for (int e = tid; e < E; e += NTHREADS) {
            int d = dstp32[e];
            if (BM_TEST(s_bm, d)) atomicAdd(&g_deg[d], 1);
        }
    }

    // ---- final sync: done-counter; non-zero blocks arrive and EXIT --------
    __syncthreads();
    if (blockIdx.x != 0) {
        if (threadIdx.x == 0) {
            __threadfence();
            atomicAdd((unsigned int*)&g_done, 1u);
        }
        return;
    }
    if (threadIdx.x == 0) {
        __threadfence();
        while (g_done < GRID - 1) { }
        __threadfence();
    }
    __syncthreads();

    // ================= P5+P6+cleanup: block 0 only =========================
    {
        int c1 = g_count1; if (c1 > CAP1) c1 = CAP1;
        int c2 = g_count2; if (c2 > CAP2) c2 = CAP2;

        // P5: layer-1 aggregation over pairs
        for (int k = threadIdx.x; k < c2; k += TPB) {
            int2 pr = g_pair[k];
            float dis = rsqrtf((float)(__ldcg(&g_deg[pr.x]) + 1));
            float did = rsqrtf((float)(__ldcg(&g_deg[pr.y]) + 1));
            atomicAdd(&g_s[pr.y], x[pr.x] * dis * did);
        }
        __syncthreads();
        __threadfence();

        // P6: layer-2 @ node N-1 + fc head (warp 0)
        if (threadIdx.x < 32) {
            int lane = threadIdx.x;
            __shared__ float sW1[16], sb1[16], sW2[128], sb2[8], sWfc[8];
            if (lane < 16) { sW1[lane] = W1[lane]; sb1[lane] = b1[lane]; }
            if (lane < 8)  { sb2[lane] = b2[lane]; sWfc[lane] = Wfc[lane]; }
            for (int k = lane; k < 128; k += 32) sW2[k] = W2[k];
            __syncwarp();

            const float dinvL = rsqrtf((float)(__ldcg(&g_deg[NLAST]) + 1));

            float agg[8];
            #pragma unroll
            for (int j = 0; j < 8; j++) agg[j] = 0.0f;

            // k in [0, c1): real edges into N-1; k == c1: appended self-loop.
            for (int k = lane; k <= c1; k += 32) {
                int u = (k == c1) ? NLAST : g_s1[k];
                float du = rsqrtf((float)(__ldcg(&g_deg[u]) + 1));
                float norm = du * dinvL;
                float su = __ldcg(&g_s[u]) + x[u] * du * du;
                float h1[16];
                #pragma unroll
                for (int j = 0; j < 16; j++)
                    h1[j] = fmaxf(fmaf(su, sW1[j], sb1[j]), 0.0f);
                #pragma unroll
                for (int j = 0; j < 8; j++) {
                    float v = 0.0f;
                    #pragma unroll
                    for (int t = 0; t < 16; t++) v = fmaf(h1[t], sW2[t * 8 + j], v);
                    agg[j] = fmaf(v, norm, agg[j]);
                }
            }
            #pragma unroll
            for (int off = 16; off > 0; off >>= 1) {
                #pragma unroll
                for (int j = 0; j < 8; j++)
                    agg[j] += __shfl_down_sync(0xffffffff, agg[j], off);
            }
            if (lane == 0) {
                float o = bfc[0];
                #pragma unroll
                for (int j = 0; j < 8; j++) {
                    float h2 = fmaxf(agg[j] + sb2[j], 0.0f);
                    o = fmaf(h2, sWfc[j], o);
                }
                out[0] = o;
            }
        }
        __syncthreads();

        // cleanup: zero all touched scratch for the next replay
        for (int k = threadIdx.x; k < c1; k += TPB) {
            int u = g_s1[k];
            g_deg[u] = 0; g_s[u] = 0.0f;
        }
        for (int k = threadIdx.x; k < c2; k += TPB) {
            int2 pr = g_pair[k];
            g_deg[pr.x] = 0; g_s[pr.x] = 0.0f;
            g_deg[pr.y] = 0; g_s[pr.y] = 0.0f;
        }
        if (threadIdx.x == 0) {
            g_deg[NLAST] = 0; g_s[NLAST] = 0.0f;
            g_count1 = 0; g_count2 = 0;
            g_done = 0u;
        }
    }
}

// ---------------------------------------------------------------------------
extern "C" void kernel_launch(void* const* d_in, const int* in_sizes, int n_in,
                              void* d_out, int out_size) {
    const float* x    = (const float*)d_in[0];
    const void*  eidx = d_in[1];
    const float* W1   = (const float*)d_in[2];
    const float* b1   = (const float*)d_in[3];
    const float* W2   = (const float*)d_in[4];
    const float* b2   = (const float*)d_in[5];
    const float* Wfc  = (const float*)d_in[6];
    const float* bfc  = (const float*)d_in[7];
    float* out = (float*)d_out;

    int E = in_sizes[1] / 2;

    gcn_fused_kernel<<<GRID, TPB>>>(eidx, x, W1, b1, W2, b2, Wfc, bfc, out, E);
}

// round 11
// speedup vs baseline: 1.1429x; 1.0725x over previous
#include <cuda_runtime.h>
#include <cuda_bf16.h>
#include <cstdint>
#include <cstddef>

#define NNODES 100000
#define NLAST  (NNODES - 1)
#define NWORDS 3125            // ceil(100000/32)
#define CAP1   4096
#define CAP2   32768
#define GRID   148
#define TPB    1024
#define NTHREADS (GRID * TPB)

// ---- scratch (device globals; zero at load; cleaned at kernel end) --------
__device__ int           g_deg[NNODES];
__device__ float         g_s[NNODES];
__device__ int           g_s1[CAP1];
__device__ int2          g_pair[CAP2];
__device__ int           g_count1;
__device__ int           g_count2;
__device__ unsigned int           g_bar_count;
__device__ volatile unsigned int  g_bar_gen;
__device__ volatile unsigned int  g_done;

// ---- software grid barrier ------------------------------------------------
__device__ __forceinline__ void grid_barrier() {
    __syncthreads();
    if (threadIdx.x == 0) {
        __threadfence();
        unsigned gen = g_bar_gen;
        unsigned arrived = atomicAdd(&g_bar_count, 1u);
        if (arrived == GRID - 1) {
            g_bar_count = 0u;
            __threadfence();
            g_bar_gen = gen + 1u;
        } else {
            while (g_bar_gen == gen) { }
        }
        __threadfence();
    }
    __syncthreads();
}

#define BM_TEST(bm, v)  (((bm)[(v) >> 5] >> ((v) & 31)) & 1u)

// ---------------------------------------------------------------------------
// chunkN > 0  -> int32 fast path: block's dst chunk staged in dynamic smem.
// chunkN == 0 -> fallback: direct global scans (also used for int64 mode).
__global__ void __launch_bounds__(TPB, 1)
gcn_fused_kernel(const void* __restrict__ eidx,
                 const float* __restrict__ x,
                 const float* __restrict__ W1, const float* __restrict__ b1,
                 const float* __restrict__ W2, const float* __restrict__ b2,
                 const float* __restrict__ Wfc, const float* __restrict__ bfc,
                 float* __restrict__ out, int E, int chunkN) {
    const int tid = blockIdx.x * TPB + threadIdx.x;

    extern __shared__ unsigned char dynsmem[];
    int*          s_chunk = (int*)dynsmem;
    unsigned int* s_bm    = (unsigned int*)(dynsmem + (size_t)chunkN * 4);

    __shared__ int sh_mode;

    // per-block dtype detect (same 256B everywhere; L2 broadcast)
    if (threadIdx.x == 0) {
        const unsigned int* w = (const unsigned int*)eidx;
        int all0 = 1;
        #pragma unroll
        for (int i = 0; i < 32; i++)
            if (w[2 * i + 1] != 0u) all0 = 0;
        sh_mode = all0;
    }
    for (int wdx = threadIdx.x; wdx < NWORDS; wdx += TPB) s_bm[wdx] = 0u;
    __syncthreads();
    const int mode = sh_mode;

    const int* __restrict__ srcp32 = (const int*)eidx;
    const int* __restrict__ dstp32 = srcp32 + E;

    // smem fast path usable?
    const bool fast = (!mode) && (chunkN > 0) &&
                      (((unsigned long long)(size_t)dstp32 & 15ull) == 0ull);

    const int base = blockIdx.x * chunkN;
    int myN = E - base; if (myN > chunkN) myN = chunkN; if (myN < 0) myN = 0;
    const int nv4 = myN >> 2;                    // myN is a multiple of 4
    const int4* __restrict__ gdv = (const int4*)(dstp32 + base);
    int4* sc4 = (int4*)s_chunk;

    // ================= P1: copy chunk to smem + test dst == N-1 ============
    if (fast) {
        int4 v[6]; int ii[6];
        #pragma unroll
        for (int k = 0; k < 6; k++) {
            ii[k] = threadIdx.x + k * TPB;
            if (ii[k] < nv4) v[k] = gdv[ii[k]];
        }
        #pragma unroll
        for (int k = 0; k < 6; k++) {
            if (ii[k] < nv4) {
                sc4[ii[k]] = v[k];
                int gi = base + 4 * ii[k];
                if (v[k].x == NLAST) { int p = atomicAdd(&g_count1, 1); if (p < CAP1) g_s1[p] = srcp32[gi + 0]; }
                if (v[k].y == NLAST) { int p = atomicAdd(&g_count1, 1); if (p < CAP1) g_s1[p] = srcp32[gi + 1]; }
                if (v[k].z == NLAST) { int p = atomicAdd(&g_count1, 1); if (p < CAP1) g_s1[p] = srcp32[gi + 2]; }
                if (v[k].w == NLAST) { int p = atomicAdd(&g_count1, 1); if (p < CAP1) g_s1[p] = srcp32[gi + 3]; }
            }
        }
    } else if (mode) {
        const long long* __restrict__ srcp = (const long long*)eidx;
        const long long* __restrict__ dstp = srcp + E;
        for (int e = tid; e < E; e += NTHREADS) {
            if ((int)dstp[e] == NLAST) { int p = atomicAdd(&g_count1, 1); if (p < CAP1) g_s1[p] = (int)srcp[e]; }
        }
    } else {
        for (int e = tid; e < E; e += NTHREADS) {
            if (dstp32[e] == NLAST) { int p = atomicAdd(&g_count1, 1); if (p < CAP1) g_s1[p] = srcp32[e]; }
        }
    }
    grid_barrier();   // barrier #1

    // build needed bitmask per-block in smem from g_s1
    {
        int c1 = g_count1; if (c1 > CAP1) c1 = CAP1;
        for (int k = threadIdx.x; k < c1; k += TPB) {
            int u = g_s1[k];
            atomicOr(&s_bm[u >> 5], 1u << (u & 31));
        }
        if (threadIdx.x == 0) atomicOr(&s_bm[NLAST >> 5], 1u << (NLAST & 31));
    }
    __syncthreads();

    // ================= P3: scan (smem) — edges into needed set =============
    if (fast) {
        for (int j = threadIdx.x; j < nv4; j += TPB) {
            int4 d4 = sc4[j];
            int gi = base + 4 * j;
            if (BM_TEST(s_bm, d4.x)) { int p = atomicAdd(&g_count2, 1); if (p < CAP2) g_pair[p] = make_int2(srcp32[gi + 0], d4.x); }
            if (BM_TEST(s_bm, d4.y)) { int p = atomicAdd(&g_count2, 1); if (p < CAP2) g_pair[p] = make_int2(srcp32[gi + 1], d4.y); }
            if (BM_TEST(s_bm, d4.z)) { int p = atomicAdd(&g_count2, 1); if (p < CAP2) g_pair[p] = make_int2(srcp32[gi + 2], d4.z); }
            if (BM_TEST(s_bm, d4.w)) { int p = atomicAdd(&g_count2, 1); if (p < CAP2) g_pair[p] = make_int2(srcp32[gi + 3], d4.w); }
        }
    } else if (mode) {
        const long long* __restrict__ srcp = (const long long*)eidx;
        const long long* __restrict__ dstp = srcp + E;
        for (int e = tid; e < E; e += NTHREADS) {
            int d = (int)dstp[e];
            if (BM_TEST(s_bm, d)) { int p = atomicAdd(&g_count2, 1); if (p < CAP2) g_pair[p] = make_int2((int)srcp[e], d); }
        }
    } else {
        for (int e = tid; e < E; e += NTHREADS) {
            int d = dstp32[e];
            if (BM_TEST(s_bm, d)) { int p = atomicAdd(&g_count2, 1); if (p < CAP2) g_pair[p] = make_int2(srcp32[e], d); }
        }
    }
    grid_barrier();   // barrier #2

    // extend bitmask with pair srcs -> need_deg set
    {
        int c2 = g_count2; if (c2 > CAP2) c2 = CAP2;
        for (int k = threadIdx.x; k < c2; k += TPB) {
            int u = g_pair[k].x;
            atomicOr(&s_bm[u >> 5], 1u << (u & 31));
        }
    }
    __syncthreads();

    // ================= P4: filtered degree scan (smem) =====================
    if (fast) {
        for (int j = threadIdx.x; j < nv4; j += TPB) {
            int4 d4 = sc4[j];
            if (BM_TEST(s_bm, d4.x)) atomicAdd(&g_deg[d4.x], 1);
            if (BM_TEST(s_bm, d4.y)) atomicAdd(&g_deg[d4.y], 1);
            if (BM_TEST(s_bm, d4.z)) atomicAdd(&g_deg[d4.z], 1);
            if (BM_TEST(s_bm, d4.w)) atomicAdd(&g_deg[d4.w], 1);
        }
    } else if (mode) {
        const long long* __restrict__ dstp = (const long long*)eidx + E;
        for (int e = tid; e < E; e += NTHREADS) {
            int d = (int)dstp[e];
            if (BM_TEST(s_bm, d)) atomicAdd(&g_deg[d], 1);
        }
    } else {
        for (int e = tid; e < E; e += NTHREADS) {
            int d = dstp32[e];
            if (BM_TEST(s_bm, d)) atomicAdd(&g_deg[d], 1);
        }
    }

    // ---- final sync: done-counter; non-zero blocks arrive and EXIT --------
    __syncthreads();
    if (blockIdx.x != 0) {
        if (threadIdx.x == 0) {
            __threadfence();
            atomicAdd((unsigned int*)&g_done, 1u);
        }
        return;
    }
    if (threadIdx.x == 0) {
        __threadfence();
        while (g_done < GRID - 1) { }
        __threadfence();
    }
    __syncthreads();

    // ================= P5+P6+cleanup: block 0 only =========================
    {
        int c1 = g_count1; if (c1 > CAP1) c1 = CAP1;
        int c2 = g_count2; if (c2 > CAP2) c2 = CAP2;

        // P5: layer-1 aggregation over pairs
        for (int k = threadIdx.x; k < c2; k += TPB) {
            int2 pr = g_pair[k];
            float dis = rsqrtf((float)(__ldcg(&g_deg[pr.x]) + 1));
            float did = rsqrtf((float)(__ldcg(&g_deg[pr.y]) + 1));
            atomicAdd(&g_s[pr.y], x[pr.x] * dis * did);
        }
        __syncthreads();
        __threadfence();

        // P6: layer-2 @ node N-1 + fc head (warp 0)
        if (threadIdx.x < 32) {
            int lane = threadIdx.x;
            __shared__ float sW1[16], sb1[16], sW2[128], sb2[8], sWfc[8];
            if (lane < 16) { sW1[lane] = W1[lane]; sb1[lane] = b1[lane]; }
            if (lane < 8)  { sb2[lane] = b2[lane]; sWfc[lane] = Wfc[lane]; }
            for (int k = lane; k < 128; k += 32) sW2[k] = W2[k];
            __syncwarp();

            const float dinvL = rsqrtf((float)(__ldcg(&g_deg[NLAST]) + 1));

            float agg[8];
            #pragma unroll
            for (int j = 0; j < 8; j++) agg[j] = 0.0f;

            // k in [0, c1): real edges into N-1; k == c1: appended self-loop.
            for (int k = lane; k <= c1; k += 32) {
                int u = (k == c1) ? NLAST : g_s1[k];
                float du = rsqrtf((float)(__ldcg(&g_deg[u]) + 1));
                float norm = du * dinvL;
                float su = __ldcg(&g_s[u]) + x[u] * du * du;
                float h1[16];
                #pragma unroll
                for (int j = 0; j < 16; j++)
                    h1[j] = fmaxf(fmaf(su, sW1[j], sb1[j]), 0.0f);
                #pragma unroll
                for (int j = 0; j < 8; j++) {
                    float v = 0.0f;
                    #pragma unroll
                    for (int t = 0; t < 16; t++) v = fmaf(h1[t], sW2[t * 8 + j], v);
                    agg[j] = fmaf(v, norm, agg[j]);
                }
            }
            #pragma unroll
            for (int off = 16; off > 0; off >>= 1) {
                #pragma unroll
                for (int j = 0; j < 8; j++)
                    agg[j] += __shfl_down_sync(0xffffffff, agg[j], off);
            }
            if (lane == 0) {
                float o = bfc[0];
                #pragma unroll
                for (int j = 0; j < 8; j++) {
                    float h2 = fmaxf(agg[j] + sb2[j], 0.0f);
                    o = fmaf(h2, sWfc[j], o);
                }
                out[0] = o;
            }
        }
        __syncthreads();

        // cleanup: zero all touched scratch for the next replay
        for (int k = threadIdx.x; k < c1; k += TPB) {
            int u = g_s1[k];
            g_deg[u] = 0; g_s[u] = 0.0f;
        }
        for (int k = threadIdx.x; k < c2; k += TPB) {
            int2 pr = g_pair[k];
            g_deg[pr.x] = 0; g_s[pr.x] = 0.0f;
            g_deg[pr.y] = 0; g_s[pr.y] = 0.0f;
        }
        if (threadIdx.x == 0) {
            g_deg[NLAST] = 0; g_s[NLAST] = 0.0f;
            g_count1 = 0; g_count2 = 0;
            g_done = 0u;
        }
    }
}

// ---------------------------------------------------------------------------
extern "C" void kernel_launch(void* const* d_in, const int* in_sizes, int n_in,
                              void* d_out, int out_size) {
    const float* x    = (const float*)d_in[0];
    const void*  eidx = d_in[1];
    const float* W1   = (const float*)d_in[2];
    const float* b1   = (const float*)d_in[3];
    const float* W2   = (const float*)d_in[4];
    const float* b2   = (const float*)d_in[5];
    const float* Wfc  = (const float*)d_in[6];
    const float* bfc  = (const float*)d_in[7];
    float* out = (float*)d_out;

    int E = in_sizes[1] / 2;

    // per-block contiguous dst chunk, staged in dynamic smem
    int chunkN = (((E + GRID - 1) / GRID) + 3) & ~3;
    size_t smem = (size_t)chunkN * 4 + (size_t)NWORDS * 4 + 16;
    bool ok = (E % 4 == 0) && ((chunkN >> 2) <= 6 * TPB) && (smem <= 200 * 1024);
    if (!ok) {
        chunkN = 0;
        smem = (size_t)NWORDS * 4 + 16;
    }
    cudaFuncSetAttribute(gcn_fused_kernel,
                         cudaFuncAttributeMaxDynamicSharedMemorySize, (int)smem);

    gcn_fused_kernel<<<GRID, TPB, smem>>>(eidx, x, W1, b1, W2, b2, Wfc, bfc,
                                          out, E, chunkN);
}